// round 6
// baseline (speedup 1.0000x reference)
#include <cuda_runtime.h>
#include <cstdint>
#include <cstddef>

#define N_ROWS 16384
#define K_TOT  16384
#define NCOL   128
#define BM     128
#define BK     32
#define KT     (K_TOT / BK)     // 512
#define NSTG   4

// SMEM layout (dynamic): A stages, then B stages, then mbarriers
#define A_PITCH_F 36            // floats per A row (144 B, 16B-aligned, conflict-free)
#define B_PITCH_F 136           // floats per B row (544 B)
#define A_STAGE_B (128 * A_PITCH_F * 4)         // 18432
#define B_STAGE_B (32  * B_PITCH_F * 4)         // 17408
#define SB_OFF    (NSTG * A_STAGE_B)            // 73728
#define MBAR_OFF  (SB_OFF + NSTG * B_STAGE_B)   // 143360
#define SMEM_TOT  (MBAR_OFF + 64)
#define STAGE_TX  32768u                        // real bytes per stage (A 16K + B 16K)

__device__ __align__(1024) float g_T[(size_t)N_ROWS * NCOL];
__device__ __align__(1024) float g_Y[(size_t)N_ROWS * NCOL];

__device__ __forceinline__ float elu_f(float x) { return x > 0.0f ? x : expm1f(x); }

__device__ __forceinline__ float round_tf32(float x) {
    uint32_t u;
    asm("cvt.rna.tf32.f32 %0, %1;" : "=r"(u) : "f"(x));
    return __uint_as_float(u);
}

__device__ __forceinline__ uint32_t smem_u32(const void* p) {
    uint32_t a;
    asm("{ .reg .u64 t; cvta.to.shared.u64 t, %1; cvt.u32.u64 %0, t; }" : "=r"(a) : "l"(p));
    return a;
}

__device__ __forceinline__ void mbar_init(uint32_t mbar, uint32_t cnt) {
    asm volatile("mbarrier.init.shared.b64 [%0], %1;" :: "r"(mbar), "r"(cnt) : "memory");
}
__device__ __forceinline__ void mbar_expect_tx(uint32_t mbar, uint32_t bytes) {
    asm volatile("mbarrier.arrive.expect_tx.shared.b64 _, [%0], %1;" :: "r"(mbar), "r"(bytes) : "memory");
}
__device__ __forceinline__ void mbar_wait(uint32_t mbar, uint32_t parity) {
    uint32_t done;
    asm volatile(
        "{\n\t.reg .pred p;\n\t"
        "mbarrier.try_wait.parity.acquire.cta.shared::cta.b64 p, [%1], %2;\n\t"
        "selp.b32 %0, 1, 0, p;\n\t}"
        : "=r"(done) : "r"(mbar), "r"(parity) : "memory");
    if (!done) {
        asm volatile(
            "{\n\t.reg .pred P1;\n\t"
            "WL_%=:\n\t"
            "mbarrier.try_wait.parity.acquire.cta.shared::cta.b64 P1, [%0], %1, 0x989680;\n\t"
            "@P1 bra.uni WD_%=;\n\t"
            "bra.uni WL_%=;\n\t"
            "WD_%=:\n\t}"
            :: "r"(mbar), "r"(parity) : "memory");
    }
}
__device__ __forceinline__ void bulk_g2s(uint32_t dst, const void* src, uint32_t bytes, uint32_t mbar) {
    asm volatile(
        "cp.async.bulk.shared::cluster.global.mbarrier::complete_tx::bytes [%0], [%1], %2, [%3];"
        :: "r"(dst), "l"(src), "r"(bytes), "r"(mbar) : "memory");
}

// ---------------------------------------------------------------------------
// k_pre / k_mid / k_final: small GEMMs (unchanged from passing R5 kernel)
// ---------------------------------------------------------------------------
__global__ void k_pre(const float* __restrict__ z, const float* __restrict__ W) {
    int h = blockIdx.y;
    int row0 = blockIdx.x * 64;
    __shared__ float xs[64][65];
    __shared__ float ws[64][65];
    int tid = threadIdx.x;
    for (int i = tid; i < 4096; i += 256) {
        int r = i >> 6, c = i & 63;
        xs[r][c] = elu_f(z[(size_t)(row0 + r) * 192 + h * 64 + c]);
        ws[r][c] = W[r * 64 + c];
    }
    __syncthreads();
    int tr = (tid >> 4) << 2, tc = (tid & 15) << 2;
    float acc[4][4] = {};
#pragma unroll 8
    for (int k = 0; k < 64; k++) {
        float xv[4], wv[4];
#pragma unroll
        for (int i = 0; i < 4; i++) xv[i] = xs[tr + i][k];
#pragma unroll
        for (int j = 0; j < 4; j++) wv[j] = ws[k][tc + j];
#pragma unroll
        for (int i = 0; i < 4; i++)
#pragma unroll
            for (int j = 0; j < 4; j++) acc[i][j] += xv[i] * wv[j];
    }
#pragma unroll
    for (int i = 0; i < 4; i++)
#pragma unroll
        for (int j = 0; j < 4; j++)
            g_T[(size_t)(row0 + tr + i) * NCOL + h * 64 + tc + j] = round_tf32(acc[i][j]);
}

__global__ void k_mid(const float* __restrict__ W) {
    int h = blockIdx.y;
    int row0 = blockIdx.x * 64;
    __shared__ float xs[64][65];
    __shared__ float ws[64][65];
    int tid = threadIdx.x;
    for (int i = tid; i < 4096; i += 256) {
        int r = i >> 6, c = i & 63;
        xs[r][c] = g_Y[(size_t)(row0 + r) * NCOL + h * 64 + c];
        ws[r][c] = W[r * 64 + c];
    }
    __syncthreads();
    int tr = (tid >> 4) << 2, tc = (tid & 15) << 2;
    float acc[4][4] = {};
#pragma unroll 8
    for (int k = 0; k < 64; k++) {
        float xv[4], wv[4];
#pragma unroll
        for (int i = 0; i < 4; i++) xv[i] = xs[tr + i][k];
#pragma unroll
        for (int j = 0; j < 4; j++) wv[j] = ws[k][tc + j];
#pragma unroll
        for (int i = 0; i < 4; i++)
#pragma unroll
            for (int j = 0; j < 4; j++) acc[i][j] += xv[i] * wv[j];
    }
#pragma unroll
    for (int i = 0; i < 4; i++)
#pragma unroll
        for (int j = 0; j < 4; j++)
            g_T[(size_t)(row0 + tr + i) * NCOL + h * 64 + tc + j] = round_tf32(acc[i][j]);
}

__global__ void k_final(const float* __restrict__ z, const float* __restrict__ Wl,
                        const float* __restrict__ bl, float* __restrict__ out) {
    int row0 = blockIdx.x * 64;
    __shared__ float xs[64][65];
    __shared__ float ws[64][65];
    int tid = threadIdx.x;
    int tr = (tid >> 4) << 2, tc = (tid & 15) << 2;
    float acc[4][4] = {};
    for (int ch = 0; ch < 3; ch++) {
        __syncthreads();
        for (int i = tid; i < 4096; i += 256) {
            int r = i >> 6, c = i & 63;
            xs[r][c] = (ch < 2) ? g_Y[(size_t)(row0 + r) * NCOL + ch * 64 + c]
                                : z[(size_t)(row0 + r) * 192 + 128 + c];
            ws[r][c] = Wl[(ch * 64 + r) * 64 + c];
        }
        __syncthreads();
#pragma unroll 8
        for (int k = 0; k < 64; k++) {
            float xv[4], wv[4];
#pragma unroll
            for (int i = 0; i < 4; i++) xv[i] = xs[tr + i][k];
#pragma unroll
            for (int j = 0; j < 4; j++) wv[j] = ws[k][tc + j];
#pragma unroll
            for (int i = 0; i < 4; i++)
#pragma unroll
                for (int j = 0; j < 4; j++) acc[i][j] += xv[i] * wv[j];
        }
    }
#pragma unroll
    for (int i = 0; i < 4; i++)
#pragma unroll
        for (int j = 0; j < 4; j++)
            out[(size_t)(row0 + tr + i) * 64 + tc + j] = acc[i][j] + bl[tc + j];
}

// ---------------------------------------------------------------------------
// k_big: Y = elu(adj @ T + bias)   via cp.async.bulk 4-stage pipeline + mma.sync
// ---------------------------------------------------------------------------
__global__ void __launch_bounds__(256, 1) k_big(const float* __restrict__ adj,
                                                const float* __restrict__ bias) {
    extern __shared__ char smem[];

    int tid = threadIdx.x;
    int lane = tid & 31, wid = tid >> 5;
    int wm = wid & 3, wn = wid >> 2;
    size_t m0 = (size_t)blockIdx.x * BM;

    uint32_t smem_base = smem_u32(smem);
    uint32_t mbar0 = smem_base + MBAR_OFF;

    // issue ktile `nk` into slot `s` (bulk engine; 1 op per participating thread)
    auto issue = [&](int s, int nk) {
        int k0 = nk * BK;
        if (tid < 128) {
            const float* src = adj + (m0 + tid) * (size_t)K_TOT + k0;
            uint32_t dst = smem_base + (uint32_t)(s * A_STAGE_B + tid * (A_PITCH_F * 4));
            bulk_g2s(dst, src, BK * 4, mbar0 + s * 8);               // 128 B
        } else if (tid < 160) {
            int r = tid - 128;
            const float* src = g_T + (size_t)(k0 + r) * NCOL;
            uint32_t dst = smem_base + (uint32_t)(SB_OFF + s * B_STAGE_B + r * (B_PITCH_F * 4));
            bulk_g2s(dst, src, NCOL * 4, mbar0 + s * 8);             // 512 B
        }
    };

    // init mbarriers
    if (tid == 0) {
#pragma unroll
        for (int s = 0; s < NSTG; s++) mbar_init(mbar0 + s * 8, 1);
    }
    __syncthreads();
    // prologue: expects first (all before any issue), then fill all stages
    if (tid == 0) {
#pragma unroll
        for (int s = 0; s < NSTG; s++) mbar_expect_tx(mbar0 + s * 8, STAGE_TX);
    }
    __syncthreads();
#pragma unroll
    for (int s = 0; s < NSTG; s++) issue(s, s);

    float acc[2][8][4];
#pragma unroll
    for (int t = 0; t < 2; t++)
#pragma unroll
        for (int j = 0; j < 8; j++)
#pragma unroll
            for (int q = 0; q < 4; q++) acc[t][j][q] = 0.0f;

    for (int kt = 0; kt < KT; kt++) {
        int s = kt & (NSTG - 1);
        uint32_t parity = (kt >> 2) & 1;
        mbar_wait(mbar0 + s * 8, parity);

        const float* sA = (const float*)(smem + s * A_STAGE_B);             // [128][36]
        const float* sB = (const float*)(smem + SB_OFF + s * B_STAGE_B);    // [32][136]

#pragma unroll
        for (int kk = 0; kk < 4; kk++) {
            int kb = kk * 8;
            uint32_t a[2][4];
#pragma unroll
            for (int t = 0; t < 2; t++) {
                int r = wm * 32 + t * 16 + (lane >> 2);
                int kc = kb + (lane & 3);
                a[t][0] = __float_as_uint(round_tf32(sA[r * A_PITCH_F + kc]));
                a[t][1] = __float_as_uint(round_tf32(sA[(r + 8) * A_PITCH_F + kc]));
                a[t][2] = __float_as_uint(round_tf32(sA[r * A_PITCH_F + kc + 4]));
                a[t][3] = __float_as_uint(round_tf32(sA[(r + 8) * A_PITCH_F + kc + 4]));
            }
#pragma unroll
            for (int j = 0; j < 8; j++) {
                int c = wn * 64 + j * 8 + (lane >> 2);
                int k1 = kb + (lane & 3);
                uint32_t b0 = __float_as_uint(sB[k1 * B_PITCH_F + c]);
                uint32_t b1 = __float_as_uint(sB[(k1 + 4) * B_PITCH_F + c]);
#pragma unroll
                for (int t = 0; t < 2; t++) {
                    asm volatile(
                        "mma.sync.aligned.m16n8k8.row.col.f32.tf32.tf32.f32 "
                        "{%0,%1,%2,%3}, {%4,%5,%6,%7}, {%8,%9}, {%0,%1,%2,%3};"
                        : "+f"(acc[t][j][0]), "+f"(acc[t][j][1]),
                          "+f"(acc[t][j][2]), "+f"(acc[t][j][3])
                        : "r"(a[t][0]), "r"(a[t][1]), "r"(a[t][2]), "r"(a[t][3]),
                          "r"(b0), "r"(b1));
                }
            }
        }

        int nk = kt + NSTG;
        if (nk < KT) {
            __syncthreads();                      // all readers done with slot s
            if (tid == 0) mbar_expect_tx(mbar0 + s * 8, STAGE_TX);
            __syncthreads();                      // expect visible before completions
            issue(s, nk);
        }
    }

    // Epilogue: + bias (per-64 broadcast), elu, store
#pragma unroll
    for (int t = 0; t < 2; t++) {
#pragma unroll
        for (int j = 0; j < 8; j++) {
            int r = (int)m0 + wm * 32 + t * 16 + (lane >> 2);
            int c = wn * 64 + j * 8 + ((lane & 3) << 1);
            float b0 = bias[c & 63];
            float b1 = bias[(c + 1) & 63];
            g_Y[(size_t)r * NCOL + c]           = elu_f(acc[t][j][0] + b0);
            g_Y[(size_t)r * NCOL + c + 1]       = elu_f(acc[t][j][1] + b1);
            g_Y[(size_t)(r + 8) * NCOL + c]     = elu_f(acc[t][j][2] + b0);
            g_Y[(size_t)(r + 8) * NCOL + c + 1] = elu_f(acc[t][j][3] + b1);
        }
    }
}

// ---------------------------------------------------------------------------
extern "C" void kernel_launch(void* const* d_in, const int* in_sizes, int n_in,
                              void* d_out, int out_size) {
    const float *z = nullptr, *adj = nullptr, *Ws = nullptr, *bs = nullptr,
                *Wl = nullptr, *bl = nullptr;
    for (int i = 0; i < n_in; i++) {
        switch (in_sizes[i]) {
            case 16384 * 192:  z   = (const float*)d_in[i]; break;
            case 268435456:    adj = (const float*)d_in[i]; break;
            case 8192:         Ws  = (const float*)d_in[i]; break;
            case 128:          bs  = (const float*)d_in[i]; break;
            case 12288:        Wl  = (const float*)d_in[i]; break;
            case 64:           bl  = (const float*)d_in[i]; break;
            default: break;
        }
    }
    float* out = (float*)d_out;

    static bool attr_set = false;
    if (!attr_set) {
        cudaFuncSetAttribute(k_big, cudaFuncAttributeMaxDynamicSharedMemorySize, SMEM_TOT);
        attr_set = true;
    }

    k_pre<<<dim3(256, 2), 256>>>(z, Ws);
    k_big<<<128, 256, SMEM_TOT>>>(adj, bs);
    k_mid<<<dim3(256, 2), 256>>>(Ws + 4096);
    k_big<<<128, 256, SMEM_TOT>>>(adj, bs + 64);
    k_final<<<256, 256>>>(z, Wl, bl, out);
}

// round 9
// speedup vs baseline: 2.0519x; 2.0519x over previous
#include <cuda_runtime.h>
#include <cuda.h>
#include <cstdint>
#include <cstddef>

#define N_ROWS 16384
#define K_TOT  16384
#define NCOL   128
#define BM     128
#define BK     32
#define KT     (K_TOT / BK)     // 512
#define NSTG   4

// k_big SMEM: 4 stages x 32KB (A 16KB: 128 rows x 128B | B 16KB: 128 rows(c) x 128B)
#define STAGE_B   32768
#define B_OFF     16384
#define CTRL_OFF  (NSTG * STAGE_B)      // 131072
#define FULL_OFF  (CTRL_OFF)
#define SMEM_TOT  (CTRL_OFF + 64)
#define STAGE_TX  32768u

__device__ __align__(1024) float g_Tt[(size_t)NCOL * K_TOT];  // B^T: [128 cols][16384 k]
__device__ __align__(1024) float g_Y[(size_t)N_ROWS * NCOL];

__device__ __forceinline__ float elu_f(float x) { return x > 0.0f ? x : expm1f(x); }

__device__ __forceinline__ float round_tf32(float x) {
    uint32_t u;
    asm("cvt.rna.tf32.f32 %0, %1;" : "=r"(u) : "f"(x));
    return __uint_as_float(u);
}

__device__ __forceinline__ uint32_t smem_u32(const void* p) {
    uint32_t a;
    asm("{ .reg .u64 t; cvta.to.shared.u64 t, %1; cvt.u32.u64 %0, t; }" : "=r"(a) : "l"(p));
    return a;
}
__device__ __forceinline__ void mbar_init(uint32_t mbar, uint32_t cnt) {
    asm volatile("mbarrier.init.shared.b64 [%0], %1;" :: "r"(mbar), "r"(cnt) : "memory");
}
__device__ __forceinline__ void mbar_expect_tx(uint32_t mbar, uint32_t bytes) {
    asm volatile("mbarrier.arrive.expect_tx.shared.b64 _, [%0], %1;" :: "r"(mbar), "r"(bytes) : "memory");
}
__device__ __forceinline__ void mbar_wait(uint32_t mbar, uint32_t parity) {
    uint32_t done;
    asm volatile(
        "{\n\t.reg .pred p;\n\t"
        "mbarrier.try_wait.parity.acquire.cta.shared::cta.b64 p, [%1], %2;\n\t"
        "selp.b32 %0, 1, 0, p;\n\t}"
        : "=r"(done) : "r"(mbar), "r"(parity) : "memory");
    if (!done) {
        asm volatile(
            "{\n\t.reg .pred P1;\n\t"
            "WL_%=:\n\t"
            "mbarrier.try_wait.parity.acquire.cta.shared::cta.b64 P1, [%0], %1, 0x989680;\n\t"
            "@P1 bra.uni WD_%=;\n\t"
            "bra.uni WL_%=;\n\t"
            "WD_%=:\n\t}"
            :: "r"(mbar), "r"(parity) : "memory");
    }
}
__device__ __forceinline__ void tma2d(uint32_t dst, const CUtensorMap* tm,
                                      int x, int y, uint32_t mbar) {
    asm volatile(
        "cp.async.bulk.tensor.2d.shared::cta.global.tile.mbarrier::complete_tx::bytes "
        "[%0], [%1, {%2, %3}], [%4];"
        :: "r"(dst), "l"(tm), "r"(x), "r"(y), "r"(mbar) : "memory");
}

// ---------------------------------------------------------------------------
// k_pre: g_Tt[h*64+c][row] = sum_k elu(z[row, h*64+k]) * W0[k][c]  (transposed out)
// ---------------------------------------------------------------------------
__global__ void k_pre(const float* __restrict__ z, const float* __restrict__ W) {
    int h = blockIdx.y;
    int row0 = blockIdx.x * 64;
    __shared__ float xs[64][65];
    __shared__ float ws[64][65];
    int tid = threadIdx.x;
    for (int i = tid; i < 4096; i += 256) {
        int r = i >> 6, c = i & 63;
        xs[r][c] = elu_f(z[(size_t)(row0 + r) * 192 + h * 64 + c]);
        ws[r][c] = W[r * 64 + c];
    }
    __syncthreads();
    int tr = (tid >> 4) << 2, tc = (tid & 15) << 2;
    float acc[4][4] = {};
#pragma unroll 8
    for (int k = 0; k < 64; k++) {
        float xv[4], wv[4];
#pragma unroll
        for (int i = 0; i < 4; i++) xv[i] = xs[tr + i][k];
#pragma unroll
        for (int j = 0; j < 4; j++) wv[j] = ws[k][tc + j];
#pragma unroll
        for (int i = 0; i < 4; i++)
#pragma unroll
            for (int j = 0; j < 4; j++) acc[i][j] += xv[i] * wv[j];
    }
    __syncthreads();
#pragma unroll
    for (int i = 0; i < 4; i++)
#pragma unroll
        for (int j = 0; j < 4; j++)
            xs[tc + j][tr + i] = round_tf32(acc[i][j]);   // transpose in smem
    __syncthreads();
    for (int i = tid; i < 4096; i += 256) {
        int c = i >> 6, r = i & 63;
        g_Tt[(size_t)(h * 64 + c) * K_TOT + row0 + r] = xs[c][r];
    }
}

// ---------------------------------------------------------------------------
// k_mid: g_Tt[h*64+c][row] = sum_k Y[row, h*64+k] * W1[k][c]  (transposed out)
// ---------------------------------------------------------------------------
__global__ void k_mid(const float* __restrict__ W) {
    int h = blockIdx.y;
    int row0 = blockIdx.x * 64;
    __shared__ float xs[64][65];
    __shared__ float ws[64][65];
    int tid = threadIdx.x;
    for (int i = tid; i < 4096; i += 256) {
        int r = i >> 6, c = i & 63;
        xs[r][c] = g_Y[(size_t)(row0 + r) * NCOL + h * 64 + c];
        ws[r][c] = W[r * 64 + c];
    }
    __syncthreads();
    int tr = (tid >> 4) << 2, tc = (tid & 15) << 2;
    float acc[4][4] = {};
#pragma unroll 8
    for (int k = 0; k < 64; k++) {
        float xv[4], wv[4];
#pragma unroll
        for (int i = 0; i < 4; i++) xv[i] = xs[tr + i][k];
#pragma unroll
        for (int j = 0; j < 4; j++) wv[j] = ws[k][tc + j];
#pragma unroll
        for (int i = 0; i < 4; i++)
#pragma unroll
            for (int j = 0; j < 4; j++) acc[i][j] += xv[i] * wv[j];
    }
    __syncthreads();
#pragma unroll
    for (int i = 0; i < 4; i++)
#pragma unroll
        for (int j = 0; j < 4; j++)
            xs[tc + j][tr + i] = round_tf32(acc[i][j]);
    __syncthreads();
    for (int i = tid; i < 4096; i += 256) {
        int c = i >> 6, r = i & 63;
        g_Tt[(size_t)(h * 64 + c) * K_TOT + row0 + r] = xs[c][r];
    }
}

// ---------------------------------------------------------------------------
// k_final: out = [Y2_s | Y2_u | z_a] @ Wl + bl
// ---------------------------------------------------------------------------
__global__ void k_final(const float* __restrict__ z, const float* __restrict__ Wl,
                        const float* __restrict__ bl, float* __restrict__ out) {
    int row0 = blockIdx.x * 64;
    __shared__ float xs[64][65];
    __shared__ float ws[64][65];
    int tid = threadIdx.x;
    int tr = (tid >> 4) << 2, tc = (tid & 15) << 2;
    float acc[4][4] = {};
    for (int ch = 0; ch < 3; ch++) {
        __syncthreads();
        for (int i = tid; i < 4096; i += 256) {
            int r = i >> 6, c = i & 63;
            xs[r][c] = (ch < 2) ? g_Y[(size_t)(row0 + r) * NCOL + ch * 64 + c]
                                : z[(size_t)(row0 + r) * 192 + 128 + c];
            ws[r][c] = Wl[(ch * 64 + r) * 64 + c];
        }
        __syncthreads();
#pragma unroll 8
        for (int k = 0; k < 64; k++) {
            float xv[4], wv[4];
#pragma unroll
            for (int i = 0; i < 4; i++) xv[i] = xs[tr + i][k];
#pragma unroll
            for (int j = 0; j < 4; j++) wv[j] = ws[k][tc + j];
#pragma unroll
            for (int i = 0; i < 4; i++)
#pragma unroll
                for (int j = 0; j < 4; j++) acc[i][j] += xv[i] * wv[j];
        }
    }
#pragma unroll
    for (int i = 0; i < 4; i++)
#pragma unroll
        for (int j = 0; j < 4; j++)
            out[(size_t)(row0 + tr + i) * 64 + tc + j] = acc[i][j] + bl[tc + j];
}

// ---------------------------------------------------------------------------
// k_big: Y = elu(adj @ Tt^T + bias)  — TMA tensor loads + mma.sync tf32
// 256 threads: 8 compute warps (4 M x 2 N); thread 0 doubles as TMA producer.
// ---------------------------------------------------------------------------
__global__ void __launch_bounds__(256, 1) k_big(
    const __grid_constant__ CUtensorMap tmA,
    const __grid_constant__ CUtensorMap tmB,
    const float* __restrict__ bias)
{
    extern __shared__ __align__(1024) char smem[];
    uint32_t sb = smem_u32(smem);
    int tid = threadIdx.x;
    int lane = tid & 31, wid = tid >> 5;
    int wm = wid & 3, wn = wid >> 2;
    int m0 = blockIdx.x * BM;

    if (tid == 0) {
#pragma unroll
        for (int s = 0; s < NSTG; s++) mbar_init(sb + FULL_OFF + s * 8, 1);
    }
    __syncthreads();
    if (tid == 0) {
#pragma unroll
        for (int s = 0; s < NSTG; s++) {
            mbar_expect_tx(sb + FULL_OFF + s * 8, STAGE_TX);
            tma2d(sb + s * STAGE_B,         &tmA, s * BK, m0, sb + FULL_OFF + s * 8);
            tma2d(sb + s * STAGE_B + B_OFF, &tmB, s * BK, 0,  sb + FULL_OFF + s * 8);
        }
    }

    float acc[2][8][4];
#pragma unroll
    for (int t = 0; t < 2; t++)
#pragma unroll
        for (int j = 0; j < 8; j++)
#pragma unroll
            for (int q = 0; q < 4; q++) acc[t][j][q] = 0.0f;

    // per-thread invariants for swizzled fragment addressing
    const uint32_t lane4 = (lane & 3) * 4;            // k sub-offset bytes
    const uint32_t xorv  = (lane >> 2) << 4;          // SW128 XOR (row&7)<<4, row&7 == lane>>2
    const int rA = wm * 32 + (lane >> 2);             // A fragment base row
    const int cB = wn * 64 + (lane >> 2);             // B fragment base col

    for (int kt = 0; kt < KT; kt++) {
        int s = kt & (NSTG - 1);
        mbar_wait(sb + FULL_OFF + s * 8, (kt >> 2) & 1);
        const char* sa = smem + s * STAGE_B;
        const char* sbu = smem + s * STAGE_B + B_OFF;

#pragma unroll
        for (int kk = 0; kk < 4; kk++) {
            uint32_t kcb = kk * 32 + lane4;           // byte offset of k within 128B row
            uint32_t v0 = kcb ^ xorv;
            uint32_t v2 = (kcb + 16) ^ xorv;

            uint32_t a[2][4];
#pragma unroll
            for (int t = 0; t < 2; t++) {
                uint32_t base = (uint32_t)(rA + t * 16) * 128;
                a[t][0] = __float_as_uint(round_tf32(*(const float*)(sa + base + v0)));
                a[t][1] = __float_as_uint(round_tf32(*(const float*)(sa + base + 1024 + v0)));
                a[t][2] = __float_as_uint(round_tf32(*(const float*)(sa + base + v2)));
                a[t][3] = __float_as_uint(round_tf32(*(const float*)(sa + base + 1024 + v2)));
            }
            uint32_t offb0 = (uint32_t)cB * 128 + v0;
            uint32_t offb1 = (uint32_t)cB * 128 + v2;
#pragma unroll
            for (int j = 0; j < 8; j++) {
                uint32_t b0 = __uint_as_float(0), b1;
                b0 = *(const uint32_t*)(sbu + offb0 + (uint32_t)j * 1024);
                b1 = *(const uint32_t*)(sbu + offb1 + (uint32_t)j * 1024);
#pragma unroll
                for (int t = 0; t < 2; t++) {
                    asm volatile(
                        "mma.sync.aligned.m16n8k8.row.col.f32.tf32.tf32.f32 "
                        "{%0,%1,%2,%3}, {%4,%5,%6,%7}, {%8,%9}, {%0,%1,%2,%3};"
                        : "+f"(acc[t][j][0]), "+f"(acc[t][j][1]),
                          "+f"(acc[t][j][2]), "+f"(acc[t][j][3])
                        : "r"(a[t][0]), "r"(a[t][1]), "r"(a[t][2]), "r"(a[t][3]),
                          "r"(b0), "r"(b1));
                }
            }
        }
        __syncthreads();                              // all warps done with slot s
        int nk = kt + NSTG;
        if (tid == 0 && nk < KT) {
            mbar_expect_tx(sb + FULL_OFF + s * 8, STAGE_TX);
            tma2d(sb + s * STAGE_B,         &tmA, nk * BK, m0, sb + FULL_OFF + s * 8);
            tma2d(sb + s * STAGE_B + B_OFF, &tmB, nk * BK, 0,  sb + FULL_OFF + s * 8);
        }
    }

    // Epilogue: + bias (per-64 broadcast), elu, store fp32 (same mapping as R5)
#pragma unroll
    for (int t = 0; t < 2; t++) {
#pragma unroll
        for (int j = 0; j < 8; j++) {
            int r = m0 + wm * 32 + t * 16 + (lane >> 2);
            int c = wn * 64 + j * 8 + ((lane & 3) << 1);
            float b0 = bias[c & 63];
            float b1 = bias[(c + 1) & 63];
            g_Y[(size_t)r * NCOL + c]           = elu_f(acc[t][j][0] + b0);
            g_Y[(size_t)r * NCOL + c + 1]       = elu_f(acc[t][j][1] + b1);
            g_Y[(size_t)(r + 8) * NCOL + c]     = elu_f(acc[t][j][2] + b0);
            g_Y[(size_t)(r + 8) * NCOL + c + 1] = elu_f(acc[t][j][3] + b1);
        }
    }
}

// ---------------------------------------------------------------------------
typedef CUresult (*EncodeFn)(CUtensorMap*, CUtensorMapDataType, cuuint32_t, void*,
                             const cuuint64_t*, const cuuint64_t*, const cuuint32_t*,
                             const cuuint32_t*, CUtensorMapInterleave, CUtensorMapSwizzle,
                             CUtensorMapL2promotion, CUtensorMapFloatOOBfill);

static void make_map(EncodeFn enc, CUtensorMap* tm, const void* base,
                     uint64_t d0, uint64_t d1) {
    cuuint64_t dims[2] = {d0, d1};
    cuuint64_t strides[1] = {d0 * 4};
    cuuint32_t box[2] = {32, 128};      // 32 floats (128B) x 128 rows, SW128
    cuuint32_t es[2] = {1, 1};
    enc(tm, CU_TENSOR_MAP_DATA_TYPE_FLOAT32, 2, (void*)base, dims, strides, box, es,
        CU_TENSOR_MAP_INTERLEAVE_NONE, CU_TENSOR_MAP_SWIZZLE_128B,
        CU_TENSOR_MAP_L2_PROMOTION_L2_128B, CU_TENSOR_MAP_FLOAT_OOB_FILL_NONE);
}

extern "C" void kernel_launch(void* const* d_in, const int* in_sizes, int n_in,
                              void* d_out, int out_size) {
    const float *z = nullptr, *adj = nullptr, *Ws = nullptr, *bs = nullptr,
                *Wl = nullptr, *bl = nullptr;
    for (int i = 0; i < n_in; i++) {
        switch (in_sizes[i]) {
            case 16384 * 192:  z   = (const float*)d_in[i]; break;
            case 268435456:    adj = (const float*)d_in[i]; break;
            case 8192:         Ws  = (const float*)d_in[i]; break;
            case 128:          bs  = (const float*)d_in[i]; break;
            case 12288:        Wl  = (const float*)d_in[i]; break;
            case 64:           bl  = (const float*)d_in[i]; break;
            default: break;
        }
    }
    float* out = (float*)d_out;

    static EncodeFn enc = nullptr;
    if (!enc) {
        void* p = nullptr;
        cudaDriverEntryPointQueryResult qr;
        cudaGetDriverEntryPointByVersion("cuTensorMapEncodeTiled", &p, 12050,
                                         cudaEnableDefault, &qr);
        enc = (EncodeFn)p;
        cudaFuncSetAttribute(k_big, cudaFuncAttributeMaxDynamicSharedMemorySize, SMEM_TOT);
    }

    void* ttp = nullptr;
    cudaGetSymbolAddress(&ttp, g_Tt);

    CUtensorMap tmA, tmB;
    make_map(enc, &tmA, adj, K_TOT, N_ROWS);   // adj: [16384 m][16384 k]
    make_map(enc, &tmB, ttp, K_TOT, NCOL);     // g_Tt: [128 c][16384 k]

    k_pre<<<dim3(256, 2), 256>>>(z, Ws);
    k_big<<<128, 256, SMEM_TOT>>>(tmA, tmB, bs);
    k_mid<<<dim3(256, 2), 256>>>(Ws + 4096);
    k_big<<<128, 256, SMEM_TOT>>>(tmA, tmB, bs + 64);
    k_final<<<256, 256>>>(z, Wl, bl, out);
}